// round 9
// baseline (speedup 1.0000x reference)
#include <cuda_runtime.h>
#include <math.h>

// CapsuleLayer dynamic routing v7: fuse agreement(i) + weighted-s(i+1) into
// one pass that computes t ONCE (5 heavy passes -> 3). Fused block = (n-chunk,
// c-group) covering ALL 64 batch rows, so the b-update is block-local:
// per n: t -> block-reduce t.v -> b += mean -> e=exp(b) -> s += e*t.

#define BB 64
#define NN 2304
#define CC 32
#define OO 16
#define II 8
#define CO 512
#define WROW 4096     // C*O*I floats per n
// pass0 (uniform s) tiling
#define NCHUNK 72
#define NPC 32
#define BG 16
#define BP 8
// fused tiling
#define NC2 144
#define NP2 16        // NN / NC2

__device__ float g_spart[(size_t)NC2 * BB * CO];  // 18.9 MB
__device__ float g_v[BB * CO];
__device__ float g_b[NN * CC];
__device__ float g_epart[NC2 * CC];
__device__ float g_inv[CC];

typedef unsigned long long u64;

__device__ __forceinline__ u64 pk2(float lo, float hi) {
    u64 r; asm("mov.b64 %0,{%1,%2};" : "=l"(r) : "f"(lo), "f"(hi)); return r;
}
__device__ __forceinline__ float2 unpk(u64 v) {
    float2 r; asm("mov.b64 {%0,%1},%2;" : "=f"(r.x), "=f"(r.y) : "l"(v)); return r;
}
__device__ __forceinline__ u64 ffma2(u64 a, u64 b, u64 c) {
    u64 d; asm("fma.rn.f32x2 %0,%1,%2,%3;" : "=l"(d) : "l"(a), "l"(b), "l"(c)); return d;
}
__device__ __forceinline__ u64 fmul2(u64 a, u64 b) {
    u64 d; asm("mul.rn.f32x2 %0,%1,%2;" : "=l"(d) : "l"(a), "l"(b)); return d;
}

// ---------------------------------------------------------------------------
// k_sj: pass0 s partials with uniform weight 1/N (v6 kernel, unchanged).
// block = (n-chunk of 32, b-group of 16); 256 threads.
// ---------------------------------------------------------------------------
__global__ __launch_bounds__(256, 2)
void k_sj(const float* __restrict__ x, const float* __restrict__ W)
{
    const int chunk = blockIdx.x;
    const int bg    = blockIdx.y;
    const int t     = threadIdx.x;
    const int n0    = chunk * NPC;

    __shared__ ulonglong2 xs[4][BP][NPC];   // 16KB

    const float4* x4 = (const float4*)x;
    {
        int bp = t >> 5;
        int nn = t & 31;
        const float4* xp0 = x4 + ((size_t)(bg * BG + 2 * bp) * NN + (n0 + nn)) * 2;
        const float4* xp1 = x4 + ((size_t)(bg * BG + 2 * bp + 1) * NN + (n0 + nn)) * 2;
        float4 a0 = xp0[0], a1 = xp0[1];
        float4 c0 = xp1[0], c1 = xp1[1];
        xs[0][bp][nn] = make_ulonglong2(pk2(a0.x, c0.x), pk2(a0.y, c0.y));
        xs[1][bp][nn] = make_ulonglong2(pk2(a0.z, c0.z), pk2(a0.w, c0.w));
        xs[2][bp][nn] = make_ulonglong2(pk2(a1.x, c1.x), pk2(a1.y, c1.y));
        xs[3][bp][nn] = make_ulonglong2(pk2(a1.z, c1.z), pk2(a1.w, c1.w));
    }
    __syncthreads();

    u64 acc0[BP], acc1[BP];
#pragma unroll
    for (int bp = 0; bp < BP; bp++) { acc0[bp] = 0ull; acc1[bp] = 0ull; }

    const float4* wp = (const float4*)(W + (size_t)n0 * WROW + (size_t)(2 * t) * II);
    float4 wa0 = wp[0], wa1 = wp[1], wb0 = wp[2], wb1 = wp[3];
    const float cw = 1.0f / (float)NN;

    for (int nn = 0; nn < NPC; nn++) {
        u64 wc0[8], wc1[8];
        {
            float m;
            m = wa0.x * cw; wc0[0] = pk2(m, m);
            m = wa0.y * cw; wc0[1] = pk2(m, m);
            m = wa0.z * cw; wc0[2] = pk2(m, m);
            m = wa0.w * cw; wc0[3] = pk2(m, m);
            m = wa1.x * cw; wc0[4] = pk2(m, m);
            m = wa1.y * cw; wc0[5] = pk2(m, m);
            m = wa1.z * cw; wc0[6] = pk2(m, m);
            m = wa1.w * cw; wc0[7] = pk2(m, m);
            m = wb0.x * cw; wc1[0] = pk2(m, m);
            m = wb0.y * cw; wc1[1] = pk2(m, m);
            m = wb0.z * cw; wc1[2] = pk2(m, m);
            m = wb0.w * cw; wc1[3] = pk2(m, m);
            m = wb1.x * cw; wc1[4] = pk2(m, m);
            m = wb1.y * cw; wc1[5] = pk2(m, m);
            m = wb1.z * cw; wc1[6] = pk2(m, m);
            m = wb1.w * cw; wc1[7] = pk2(m, m);
        }
        if (nn + 1 < NPC) {
            const float4* wn = wp + (size_t)(nn + 1) * (WROW / 4);
            wa0 = wn[0]; wa1 = wn[1]; wb0 = wn[2]; wb1 = wn[3];
        }
#pragma unroll
        for (int bp = 0; bp < BP; bp++) {
            ulonglong2 x01 = xs[0][bp][nn];
            ulonglong2 x23 = xs[1][bp][nn];
            ulonglong2 x45 = xs[2][bp][nn];
            ulonglong2 x67 = xs[3][bp][nn];
            u64 a0 = acc0[bp], a1 = acc1[bp];
            a0 = ffma2(wc0[0], x01.x, a0); a1 = ffma2(wc1[0], x01.x, a1);
            a0 = ffma2(wc0[1], x01.y, a0); a1 = ffma2(wc1[1], x01.y, a1);
            a0 = ffma2(wc0[2], x23.x, a0); a1 = ffma2(wc1[2], x23.x, a1);
            a0 = ffma2(wc0[3], x23.y, a0); a1 = ffma2(wc1[3], x23.y, a1);
            a0 = ffma2(wc0[4], x45.x, a0); a1 = ffma2(wc1[4], x45.x, a1);
            a0 = ffma2(wc0[5], x45.y, a0); a1 = ffma2(wc1[5], x45.y, a1);
            a0 = ffma2(wc0[6], x67.x, a0); a1 = ffma2(wc1[6], x67.x, a1);
            a0 = ffma2(wc0[7], x67.y, a0); a1 = ffma2(wc1[7], x67.y, a1);
            acc0[bp] = a0; acc1[bp] = a1;
        }
    }

    float* sp = g_spart + ((size_t)chunk * BB + (size_t)bg * BG) * CO + 2 * t;
#pragma unroll
    for (int bp = 0; bp < BP; bp++) {
        float2 f0 = unpk(acc0[bp]);
        float2 f1 = unpk(acc1[bp]);
        *(float2*)(sp + (size_t)(2 * bp) * CO)     = make_float2(f0.x, f1.x);
        *(float2*)(sp + (size_t)(2 * bp + 1) * CO) = make_float2(f0.y, f1.y);
    }
}

// ---------------------------------------------------------------------------
// k_fused: agreement + b-update + e=exp(b) + weighted-s in ONE pass (t
// computed once per n). block = (n-chunk of 16, c-group of 8c); 512 threads:
// bq = t>>6 owns 8 b (4 b-pairs); cp = t&63: c_local = cp>>3, opair = cp&7.
// ---------------------------------------------------------------------------
__global__ __launch_bounds__(512)
void k_fused(const float* __restrict__ x, const float* __restrict__ W, int first)
{
    const int chunk = blockIdx.x;
    const int cg    = blockIdx.y;
    const int t     = threadIdx.x;
    const int n0    = chunk * NP2;
    const int bq    = t >> 6;
    const int cp    = t & 63;
    const int cl    = cp >> 3;
    const int opair = cp & 7;
    const int co0   = (cg * 8 + cl) * OO + opair * 2;

    __shared__ ulonglong2 xs[4][32][NP2];   // 32KB: all 64 b (32 b-pairs)
    __shared__ float ared[8][8];            // [bq][c_local]
    __shared__ float es_sm[8];
    __shared__ float bs[NP2][8];            // b_old per (n, c_local)

    // x tile: 512 threads, one (b-pair, n) each
    {
        int bpg = t >> 4;
        int nn  = t & 15;
        const float4* x4 = (const float4*)x;
        const float4* xp0 = x4 + ((size_t)(2 * bpg) * NN + (n0 + nn)) * 2;
        const float4* xp1 = x4 + ((size_t)(2 * bpg + 1) * NN + (n0 + nn)) * 2;
        float4 a0 = xp0[0], a1 = xp0[1];
        float4 c0 = xp1[0], c1 = xp1[1];
        xs[0][bpg][nn] = make_ulonglong2(pk2(a0.x, c0.x), pk2(a0.y, c0.y));
        xs[1][bpg][nn] = make_ulonglong2(pk2(a0.z, c0.z), pk2(a0.w, c0.w));
        xs[2][bpg][nn] = make_ulonglong2(pk2(a1.x, c1.x), pk2(a1.y, c1.y));
        xs[3][bpg][nn] = make_ulonglong2(pk2(a1.z, c1.z), pk2(a1.w, c1.w));
    }
    if (!first) {
        for (int i = t; i < NP2 * 8; i += 512) {
            int nn = i >> 3, c2 = i & 7;
            bs[nn][c2] = g_b[(size_t)(n0 + nn) * CC + cg * 8 + c2];
        }
    }

    // v for this thread's 2 co x 8 b, b-pair packed
    u64 vp0[4], vp1[4];
#pragma unroll
    for (int j = 0; j < 4; j++) {
        int be = bq * 8 + 2 * j;
        float2 a = *(const float2*)(g_v + (size_t)be * CO + co0);
        float2 b = *(const float2*)(g_v + (size_t)(be + 1) * CO + co0);
        vp0[j] = pk2(a.x, b.x);
        vp1[j] = pk2(a.y, b.y);
    }
    __syncthreads();

    u64 acc0[4], acc1[4];
#pragma unroll
    for (int j = 0; j < 4; j++) { acc0[j] = 0ull; acc1[j] = 0ull; }
    float esum_local = 0.0f;

    for (int nn = 0; nn < NP2; nn++) {
        const float4* wpn = (const float4*)(W + (size_t)(n0 + nn) * WROW + (size_t)co0 * II);
        float4 wa0 = wpn[0], wa1 = wpn[1], wb0 = wpn[2], wb1 = wpn[3];
        u64 wd0[8], wd1[8];
        wd0[0] = pk2(wa0.x, wa0.x); wd0[1] = pk2(wa0.y, wa0.y);
        wd0[2] = pk2(wa0.z, wa0.z); wd0[3] = pk2(wa0.w, wa0.w);
        wd0[4] = pk2(wa1.x, wa1.x); wd0[5] = pk2(wa1.y, wa1.y);
        wd0[6] = pk2(wa1.z, wa1.z); wd0[7] = pk2(wa1.w, wa1.w);
        wd1[0] = pk2(wb0.x, wb0.x); wd1[1] = pk2(wb0.y, wb0.y);
        wd1[2] = pk2(wb0.z, wb0.z); wd1[3] = pk2(wb0.w, wb0.w);
        wd1[4] = pk2(wb1.x, wb1.x); wd1[5] = pk2(wb1.y, wb1.y);
        wd1[6] = pk2(wb1.z, wb1.z); wd1[7] = pk2(wb1.w, wb1.w);

        u64 t0[4], t1[4];
        u64 pacc = 0ull;
#pragma unroll
        for (int j = 0; j < 4; j++) {
            int bpg = bq * 4 + j;
            ulonglong2 x01 = xs[0][bpg][nn];
            ulonglong2 x23 = xs[1][bpg][nn];
            ulonglong2 x45 = xs[2][bpg][nn];
            ulonglong2 x67 = xs[3][bpg][nn];
            u64 a0 = fmul2(wd0[0], x01.x);
            u64 a1 = fmul2(wd1[0], x01.x);
            a0 = ffma2(wd0[1], x01.y, a0); a1 = ffma2(wd1[1], x01.y, a1);
            a0 = ffma2(wd0[2], x23.x, a0); a1 = ffma2(wd1[2], x23.x, a1);
            a0 = ffma2(wd0[3], x23.y, a0); a1 = ffma2(wd1[3], x23.y, a1);
            a0 = ffma2(wd0[4], x45.x, a0); a1 = ffma2(wd1[4], x45.x, a1);
            a0 = ffma2(wd0[5], x45.y, a0); a1 = ffma2(wd1[5], x45.y, a1);
            a0 = ffma2(wd0[6], x67.x, a0); a1 = ffma2(wd1[6], x67.x, a1);
            a0 = ffma2(wd0[7], x67.y, a0); a1 = ffma2(wd1[7], x67.y, a1);
            t0[j] = a0; t1[j] = a1;
            pacc = ffma2(a0, vp0[j], pacc);
            pacc = ffma2(a1, vp1[j], pacc);
        }
        float2 pv = unpk(pacc);
        float p = pv.x + pv.y;
        p += __shfl_down_sync(0xffffffffu, p, 4, 8);
        p += __shfl_down_sync(0xffffffffu, p, 2, 8);
        p += __shfl_down_sync(0xffffffffu, p, 1, 8);
        if (opair == 0) ared[bq][cl] = p;
        __syncthreads();
        if (t < 8) {
            float a = ared[0][t] + ared[1][t] + ared[2][t] + ared[3][t]
                    + ared[4][t] + ared[5][t] + ared[6][t] + ared[7][t];
            a *= (1.0f / (float)BB);
            float bold = first ? 0.0f : bs[nn][t];
            float bnew = bold + a;
            if (first)
                g_b[(size_t)(n0 + nn) * CC + cg * 8 + t] = bnew;
            float e = expf(bnew);
            es_sm[t] = e;
            esum_local += e;
        }
        __syncthreads();
        float e = es_sm[cl];
        u64 ed = pk2(e, e);
#pragma unroll
        for (int j = 0; j < 4; j++) {
            acc0[j] = ffma2(ed, t0[j], acc0[j]);
            acc1[j] = ffma2(ed, t1[j], acc1[j]);
        }
    }

    // store s partials for this (chunk, co slice), all 64 b
    float* sp = g_spart + (size_t)chunk * BB * CO + co0;
#pragma unroll
    for (int j = 0; j < 4; j++) {
        int be = bq * 8 + 2 * j;
        float2 f0 = unpk(acc0[j]);   // (s[b_even,co0], s[b_odd,co0])
        float2 f1 = unpk(acc1[j]);
        *(float2*)(sp + (size_t)be * CO)       = make_float2(f0.x, f1.x);
        *(float2*)(sp + (size_t)(be + 1) * CO) = make_float2(f0.y, f1.y);
    }
    if (t < 8)
        g_epart[chunk * CC + cg * 8 + t] = esum_local;
}

// ---------------------------------------------------------------------------
// k_squash: float2 partial reduce over nch chunks + squash. 128 blocks x 128.
// ---------------------------------------------------------------------------
__global__ void k_squash(float* __restrict__ dout, int nch, int uniform, int final_pass)
{
    int id2 = blockIdx.x * 128 + threadIdx.x;   // 0..16383 (b*256 + co/2)
    const float2* sp = (const float2*)g_spart;
    float sx = 0.0f, sy = 0.0f;
#pragma unroll 4
    for (int ch = 0; ch < nch; ch++) {
        float2 p = sp[(size_t)ch * 16384 + id2];
        sx += p.x; sy += p.y;
    }
    int c = (id2 >> 3) & 31;
    float scale = uniform ? 1.0f : g_inv[c];
    sx *= scale; sy *= scale;
    float2 v;
    v.x = sx * fabsf(sx) / (1.0f + sx * sx);
    v.y = sy * fabsf(sy) / (1.0f + sy * sy);
    if (final_pass) ((float2*)dout)[id2] = v;
    else            ((float2*)g_v)[id2]  = v;
}

// ---------------------------------------------------------------------------
// k_esum: per-c total of e over 144 chunk partials, store reciprocal.
// ---------------------------------------------------------------------------
__global__ void k_esum()
{
    const int c = blockIdx.x;
    const int t = threadIdx.x;
    __shared__ float red[256];
    float s = 0.0f;
    for (int i = t; i < NC2; i += 256)
        s += g_epart[i * CC + c];
    red[t] = s;
    __syncthreads();
    for (int off = 128; off > 0; off >>= 1) {
        if (t < off) red[t] += red[t + off];
        __syncthreads();
    }
    if (t == 0) g_inv[c] = 1.0f / red[0];
}

// ---------------------------------------------------------------------------
extern "C" void kernel_launch(void* const* d_in, const int* in_sizes, int n_in,
                              void* d_out, int out_size)
{
    const float* x = (const float*)d_in[0];   // [B, N, I]
    const float* W = (const float*)d_in[1];   // [N, C, O, I]
    float* out = (float*)d_out;               // [B, C, O, 1]

    dim3 g0(NCHUNK, 4);
    dim3 gf(NC2, 4);

    // iteration 0: uniform-weight s -> v0
    k_sj<<<g0, 256>>>(x, W);
    k_squash<<<128, 128>>>(out, NCHUNK, 1, 0);

    // fused: agreement(v0) -> b1, e1 -> s1 partials
    k_fused<<<gf, 512>>>(x, W, 1);
    k_esum<<<CC, 256>>>();
    k_squash<<<128, 128>>>(out, NC2, 0, 0);

    // fused: agreement(v1) -> b2, e2 -> s2 partials
    k_fused<<<gf, 512>>>(x, W, 0);
    k_esum<<<CC, 256>>>();
    k_squash<<<128, 128>>>(out, NC2, 0, 1);
}

// round 10
// speedup vs baseline: 1.1558x; 1.1558x over previous
#include <cuda_runtime.h>
#include <math.h>

// CapsuleLayer dynamic routing v8: v7 fusion (agreement + b-update + exp +
// weighted-s in one pass, t computed once) re-scheduled: 256-thread blocks
// with 2 blocks/SM (barrier tails overlap across blocks) + W prefetch.

#define BB 64
#define NN 2304
#define CC 32
#define OO 16
#define II 8
#define CO 512
#define WROW 4096     // C*O*I floats per n
// pass0 tiling (v6 k_sj)
#define NCHUNK 72
#define NPC 32
#define BG 16
#define BP 8
// fused tiling
#define NC2 144
#define NP2 16        // NN / NC2

__device__ float g_spart[(size_t)NC2 * BB * CO];  // 18.9 MB
__device__ float g_v[BB * CO];
__device__ float g_b[NN * CC];
__device__ float g_epart[NC2 * CC];
__device__ float g_inv[CC];

typedef unsigned long long u64;

__device__ __forceinline__ u64 pk2(float lo, float hi) {
    u64 r; asm("mov.b64 %0,{%1,%2};" : "=l"(r) : "f"(lo), "f"(hi)); return r;
}
__device__ __forceinline__ float2 unpk(u64 v) {
    float2 r; asm("mov.b64 {%0,%1},%2;" : "=f"(r.x), "=f"(r.y) : "l"(v)); return r;
}
__device__ __forceinline__ u64 ffma2(u64 a, u64 b, u64 c) {
    u64 d; asm("fma.rn.f32x2 %0,%1,%2,%3;" : "=l"(d) : "l"(a), "l"(b), "l"(c)); return d;
}
__device__ __forceinline__ u64 fmul2(u64 a, u64 b) {
    u64 d; asm("mul.rn.f32x2 %0,%1,%2;" : "=l"(d) : "l"(a), "l"(b)); return d;
}

// ---------------------------------------------------------------------------
// k_sj: pass0 s partials with uniform weight 1/N (v6 kernel, proven).
// ---------------------------------------------------------------------------
__global__ __launch_bounds__(256, 2)
void k_sj(const float* __restrict__ x, const float* __restrict__ W)
{
    const int chunk = blockIdx.x;
    const int bg    = blockIdx.y;
    const int t     = threadIdx.x;
    const int n0    = chunk * NPC;

    __shared__ ulonglong2 xs[4][BP][NPC];   // 16KB

    const float4* x4 = (const float4*)x;
    {
        int bp = t >> 5;
        int nn = t & 31;
        const float4* xp0 = x4 + ((size_t)(bg * BG + 2 * bp) * NN + (n0 + nn)) * 2;
        const float4* xp1 = x4 + ((size_t)(bg * BG + 2 * bp + 1) * NN + (n0 + nn)) * 2;
        float4 a0 = xp0[0], a1 = xp0[1];
        float4 c0 = xp1[0], c1 = xp1[1];
        xs[0][bp][nn] = make_ulonglong2(pk2(a0.x, c0.x), pk2(a0.y, c0.y));
        xs[1][bp][nn] = make_ulonglong2(pk2(a0.z, c0.z), pk2(a0.w, c0.w));
        xs[2][bp][nn] = make_ulonglong2(pk2(a1.x, c1.x), pk2(a1.y, c1.y));
        xs[3][bp][nn] = make_ulonglong2(pk2(a1.z, c1.z), pk2(a1.w, c1.w));
    }
    __syncthreads();

    u64 acc0[BP], acc1[BP];
#pragma unroll
    for (int bp = 0; bp < BP; bp++) { acc0[bp] = 0ull; acc1[bp] = 0ull; }

    const float4* wp = (const float4*)(W + (size_t)n0 * WROW + (size_t)(2 * t) * II);
    float4 wa0 = wp[0], wa1 = wp[1], wb0 = wp[2], wb1 = wp[3];
    const float cw = 1.0f / (float)NN;

    for (int nn = 0; nn < NPC; nn++) {
        u64 wc0[8], wc1[8];
        {
            float m;
            m = wa0.x * cw; wc0[0] = pk2(m, m);
            m = wa0.y * cw; wc0[1] = pk2(m, m);
            m = wa0.z * cw; wc0[2] = pk2(m, m);
            m = wa0.w * cw; wc0[3] = pk2(m, m);
            m = wa1.x * cw; wc0[4] = pk2(m, m);
            m = wa1.y * cw; wc0[5] = pk2(m, m);
            m = wa1.z * cw; wc0[6] = pk2(m, m);
            m = wa1.w * cw; wc0[7] = pk2(m, m);
            m = wb0.x * cw; wc1[0] = pk2(m, m);
            m = wb0.y * cw; wc1[1] = pk2(m, m);
            m = wb0.z * cw; wc1[2] = pk2(m, m);
            m = wb0.w * cw; wc1[3] = pk2(m, m);
            m = wb1.x * cw; wc1[4] = pk2(m, m);
            m = wb1.y * cw; wc1[5] = pk2(m, m);
            m = wb1.z * cw; wc1[6] = pk2(m, m);
            m = wb1.w * cw; wc1[7] = pk2(m, m);
        }
        if (nn + 1 < NPC) {
            const float4* wn = wp + (size_t)(nn + 1) * (WROW / 4);
            wa0 = wn[0]; wa1 = wn[1]; wb0 = wn[2]; wb1 = wn[3];
        }
#pragma unroll
        for (int bp = 0; bp < BP; bp++) {
            ulonglong2 x01 = xs[0][bp][nn];
            ulonglong2 x23 = xs[1][bp][nn];
            ulonglong2 x45 = xs[2][bp][nn];
            ulonglong2 x67 = xs[3][bp][nn];
            u64 a0 = acc0[bp], a1 = acc1[bp];
            a0 = ffma2(wc0[0], x01.x, a0); a1 = ffma2(wc1[0], x01.x, a1);
            a0 = ffma2(wc0[1], x01.y, a0); a1 = ffma2(wc1[1], x01.y, a1);
            a0 = ffma2(wc0[2], x23.x, a0); a1 = ffma2(wc1[2], x23.x, a1);
            a0 = ffma2(wc0[3], x23.y, a0); a1 = ffma2(wc1[3], x23.y, a1);
            a0 = ffma2(wc0[4], x45.x, a0); a1 = ffma2(wc1[4], x45.x, a1);
            a0 = ffma2(wc0[5], x45.y, a0); a1 = ffma2(wc1[5], x45.y, a1);
            a0 = ffma2(wc0[6], x67.x, a0); a1 = ffma2(wc1[6], x67.x, a1);
            a0 = ffma2(wc0[7], x67.y, a0); a1 = ffma2(wc1[7], x67.y, a1);
            acc0[bp] = a0; acc1[bp] = a1;
        }
    }

    float* sp = g_spart + ((size_t)chunk * BB + (size_t)bg * BG) * CO + 2 * t;
#pragma unroll
    for (int bp = 0; bp < BP; bp++) {
        float2 f0 = unpk(acc0[bp]);
        float2 f1 = unpk(acc1[bp]);
        *(float2*)(sp + (size_t)(2 * bp) * CO)     = make_float2(f0.x, f1.x);
        *(float2*)(sp + (size_t)(2 * bp + 1) * CO) = make_float2(f0.y, f1.y);
    }
}

// ---------------------------------------------------------------------------
// k_fused: agreement + b-update + e=exp(b) + weighted-s, t computed once per n.
// 256 threads, 2 blocks/SM. block = (n-chunk of 16, c-group of 4 c).
// bq = t>>5 owns 8 b (4 b-pairs); cp = t&31: cl = cp>>3 (c), opair = cp&7.
// ---------------------------------------------------------------------------
__global__ __launch_bounds__(256, 2)
void k_fused(const float* __restrict__ x, const float* __restrict__ W, int first)
{
    const int chunk = blockIdx.x;
    const int cg    = blockIdx.y;          // 0..7, 4 c each
    const int t     = threadIdx.x;
    const int n0    = chunk * NP2;
    const int bq    = t >> 5;
    const int cp    = t & 31;
    const int cl    = cp >> 3;
    const int opair = cp & 7;
    const int cglob = cg * 4 + cl;
    const int co0   = cglob * OO + opair * 2;

    __shared__ ulonglong2 xs[4][32][NP2];   // 32KB: all 64 b (32 b-pairs)
    __shared__ float ared[8][4];            // [bq][cl]
    __shared__ float es_sm[4];
    __shared__ float bs[NP2][4];

    // x tile: 512 (b-pair, n) entries, 2 per thread
    {
        const float4* x4 = (const float4*)x;
        for (int i = t; i < 32 * NP2; i += 256) {
            int bpg = i >> 4;
            int nn  = i & 15;
            const float4* xp0 = x4 + ((size_t)(2 * bpg) * NN + (n0 + nn)) * 2;
            const float4* xp1 = x4 + ((size_t)(2 * bpg + 1) * NN + (n0 + nn)) * 2;
            float4 a0 = xp0[0], a1 = xp0[1];
            float4 c0 = xp1[0], c1 = xp1[1];
            xs[0][bpg][nn] = make_ulonglong2(pk2(a0.x, c0.x), pk2(a0.y, c0.y));
            xs[1][bpg][nn] = make_ulonglong2(pk2(a0.z, c0.z), pk2(a0.w, c0.w));
            xs[2][bpg][nn] = make_ulonglong2(pk2(a1.x, c1.x), pk2(a1.y, c1.y));
            xs[3][bpg][nn] = make_ulonglong2(pk2(a1.z, c1.z), pk2(a1.w, c1.w));
        }
    }
    if (!first) {
        for (int i = t; i < NP2 * 4; i += 256) {
            int nn = i >> 2, c2 = i & 3;
            bs[nn][c2] = g_b[(size_t)(n0 + nn) * CC + cg * 4 + c2];
        }
    }

    // v for this thread's 2 co x 8 b, b-pair packed
    u64 vp0[4], vp1[4];
#pragma unroll
    for (int j = 0; j < 4; j++) {
        int be = bq * 8 + 2 * j;
        float2 a = *(const float2*)(g_v + (size_t)be * CO + co0);
        float2 b = *(const float2*)(g_v + (size_t)(be + 1) * CO + co0);
        vp0[j] = pk2(a.x, b.x);
        vp1[j] = pk2(a.y, b.y);
    }
    __syncthreads();

    u64 acc0[4], acc1[4];
#pragma unroll
    for (int j = 0; j < 4; j++) { acc0[j] = 0ull; acc1[j] = 0ull; }
    float esum_local = 0.0f;

    // preload W row for nn=0
    const float4* wp = (const float4*)(W + (size_t)n0 * WROW + (size_t)co0 * II);
    float4 wa0 = wp[0], wa1 = wp[1], wb0 = wp[2], wb1 = wp[3];

    for (int nn = 0; nn < NP2; nn++) {
        // pack wd from current regs (ALU pipe), then prefetch next n's W
        u64 wd0[8], wd1[8];
        wd0[0] = pk2(wa0.x, wa0.x); wd0[1] = pk2(wa0.y, wa0.y);
        wd0[2] = pk2(wa0.z, wa0.z); wd0[3] = pk2(wa0.w, wa0.w);
        wd0[4] = pk2(wa1.x, wa1.x); wd0[5] = pk2(wa1.y, wa1.y);
        wd0[6] = pk2(wa1.z, wa1.z); wd0[7] = pk2(wa1.w, wa1.w);
        wd1[0] = pk2(wb0.x, wb0.x); wd1[1] = pk2(wb0.y, wb0.y);
        wd1[2] = pk2(wb0.z, wb0.z); wd1[3] = pk2(wb0.w, wb0.w);
        wd1[4] = pk2(wb1.x, wb1.x); wd1[5] = pk2(wb1.y, wb1.y);
        wd1[6] = pk2(wb1.z, wb1.z); wd1[7] = pk2(wb1.w, wb1.w);
        if (nn + 1 < NP2) {
            const float4* wn = wp + (size_t)(nn + 1) * (WROW / 4);
            wa0 = wn[0]; wa1 = wn[1]; wb0 = wn[2]; wb1 = wn[3];
        }

        u64 t0[4], t1[4];
        u64 pacc = 0ull;
#pragma unroll
        for (int j = 0; j < 4; j++) {
            int bpg = bq * 4 + j;
            ulonglong2 x01 = xs[0][bpg][nn];
            ulonglong2 x23 = xs[1][bpg][nn];
            ulonglong2 x45 = xs[2][bpg][nn];
            ulonglong2 x67 = xs[3][bpg][nn];
            u64 a0 = fmul2(wd0[0], x01.x);
            u64 a1 = fmul2(wd1[0], x01.x);
            a0 = ffma2(wd0[1], x01.y, a0); a1 = ffma2(wd1[1], x01.y, a1);
            a0 = ffma2(wd0[2], x23.x, a0); a1 = ffma2(wd1[2], x23.x, a1);
            a0 = ffma2(wd0[3], x23.y, a0); a1 = ffma2(wd1[3], x23.y, a1);
            a0 = ffma2(wd0[4], x45.x, a0); a1 = ffma2(wd1[4], x45.x, a1);
            a0 = ffma2(wd0[5], x45.y, a0); a1 = ffma2(wd1[5], x45.y, a1);
            a0 = ffma2(wd0[6], x67.x, a0); a1 = ffma2(wd1[6], x67.x, a1);
            a0 = ffma2(wd0[7], x67.y, a0); a1 = ffma2(wd1[7], x67.y, a1);
            t0[j] = a0; t1[j] = a1;
            pacc = ffma2(a0, vp0[j], pacc);
            pacc = ffma2(a1, vp1[j], pacc);
        }
        float2 pv = unpk(pacc);
        float p = pv.x + pv.y;
        p += __shfl_down_sync(0xffffffffu, p, 4, 8);
        p += __shfl_down_sync(0xffffffffu, p, 2, 8);
        p += __shfl_down_sync(0xffffffffu, p, 1, 8);
        if (opair == 0) ared[bq][cl] = p;
        __syncthreads();
        if (t < 4) {
            float a = ared[0][t] + ared[1][t] + ared[2][t] + ared[3][t]
                    + ared[4][t] + ared[5][t] + ared[6][t] + ared[7][t];
            a *= (1.0f / (float)BB);
            float bold = first ? 0.0f : bs[nn][t];
            float bnew = bold + a;
            if (first)
                g_b[(size_t)(n0 + nn) * CC + cg * 4 + t] = bnew;
            float e = expf(bnew);
            es_sm[t] = e;
            esum_local += e;
        }
        __syncthreads();
        float e = es_sm[cl];
        u64 ed = pk2(e, e);
#pragma unroll
        for (int j = 0; j < 4; j++) {
            acc0[j] = ffma2(ed, t0[j], acc0[j]);
            acc1[j] = ffma2(ed, t1[j], acc1[j]);
        }
    }

    float* sp = g_spart + (size_t)chunk * BB * CO + co0;
#pragma unroll
    for (int j = 0; j < 4; j++) {
        int be = bq * 8 + 2 * j;
        float2 f0 = unpk(acc0[j]);
        float2 f1 = unpk(acc1[j]);
        *(float2*)(sp + (size_t)be * CO)       = make_float2(f0.x, f1.x);
        *(float2*)(sp + (size_t)(be + 1) * CO) = make_float2(f0.y, f1.y);
    }
    if (t < 4)
        g_epart[chunk * CC + cg * 4 + t] = esum_local;
}

// ---------------------------------------------------------------------------
// k_squash: float2 partial reduce over nch chunks + squash. 128 blocks x 128.
// ---------------------------------------------------------------------------
__global__ void k_squash(float* __restrict__ dout, int nch, int uniform, int final_pass)
{
    int id2 = blockIdx.x * 128 + threadIdx.x;   // 0..16383 (b*256 + co/2)
    const float2* sp = (const float2*)g_spart;
    float sx = 0.0f, sy = 0.0f;
#pragma unroll 4
    for (int ch = 0; ch < nch; ch++) {
        float2 p = sp[(size_t)ch * 16384 + id2];
        sx += p.x; sy += p.y;
    }
    int c = (id2 >> 3) & 31;
    float scale = uniform ? 1.0f : g_inv[c];
    sx *= scale; sy *= scale;
    float2 v;
    v.x = sx * fabsf(sx) / (1.0f + sx * sx);
    v.y = sy * fabsf(sy) / (1.0f + sy * sy);
    if (final_pass) ((float2*)dout)[id2] = v;
    else            ((float2*)g_v)[id2]  = v;
}

// ---------------------------------------------------------------------------
// k_esum: per-c total of e over 144 chunk partials, store reciprocal.
// ---------------------------------------------------------------------------
__global__ void k_esum()
{
    const int c = blockIdx.x;
    const int t = threadIdx.x;
    __shared__ float red[256];
    float s = 0.0f;
    for (int i = t; i < NC2; i += 256)
        s += g_epart[i * CC + c];
    red[t] = s;
    __syncthreads();
    for (int off = 128; off > 0; off >>= 1) {
        if (t < off) red[t] += red[t + off];
        __syncthreads();
    }
    if (t == 0) g_inv[c] = 1.0f / red[0];
}

// ---------------------------------------------------------------------------
extern "C" void kernel_launch(void* const* d_in, const int* in_sizes, int n_in,
                              void* d_out, int out_size)
{
    const float* x = (const float*)d_in[0];   // [B, N, I]
    const float* W = (const float*)d_in[1];   // [N, C, O, I]
    float* out = (float*)d_out;               // [B, C, O, 1]

    dim3 g0(NCHUNK, 4);
    dim3 gf(NC2, 8);

    // iteration 0: uniform-weight s -> v0
    k_sj<<<g0, 256>>>(x, W);
    k_squash<<<128, 128>>>(out, NCHUNK, 1, 0);

    // fused: agreement(v0) -> b1, e1 -> s1 partials
    k_fused<<<gf, 256>>>(x, W, 1);
    k_esum<<<CC, 256>>>();
    k_squash<<<128, 128>>>(out, NC2, 0, 0);

    // fused: agreement(v1) -> b2, e2 -> s2 partials
    k_fused<<<gf, 256>>>(x, W, 0);
    k_esum<<<CC, 256>>>();
    k_squash<<<128, 128>>>(out, NC2, 0, 1);
}